// round 5
// baseline (speedup 1.0000x reference)
#include <cuda_runtime.h>
#include <cstdint>

#define T_STEPS 50
#define BATCH   1024
#define NIN     784
#define HID     256
#define NL      10
#define NROWS   (T_STEPS * BATCH)   // 51200

// scratch (static device arrays; no runtime allocation)
__device__ float g_wiT[NIN * HID];      // WiT[k][h] = Wi[h][k]
__device__ float g_wrT[HID * HID];      // WrT[k][h] = Wr[h][k]
__device__ float g_xw[NROWS * HID];     // XW[t*B+b][h], split-K-8 rounding

typedef unsigned long long ull;

// ---------------- packed f32x2 helpers (2 independent IEEE-rn fp32 lanes) ---
__device__ __forceinline__ ull f2_add(ull a, ull b) {
    ull r; asm("add.rn.f32x2 %0, %1, %2;" : "=l"(r) : "l"(a), "l"(b)); return r;
}

// ---------------------------------------------------------------------------
// K0: build WiT and WrT
// ---------------------------------------------------------------------------
__global__ void k0_prep(const float* __restrict__ Wi, const float* __restrict__ Wr) {
    int idx = blockIdx.x * 256 + threadIdx.x;
    if (idx < NIN * HID) {
        int k = idx >> 8;
        int h = idx & 255;
        g_wiT[idx] = Wi[h * NIN + k];
    }
    if (idx < HID * HID) {
        int k = idx >> 8;
        int h = idx & 255;
        g_wrT[idx] = Wr[h * HID + k];
    }
}

// ---------------------------------------------------------------------------
// K1: XW[r][h] = split-K=8 sum over {k : x[r][k]=1} of WiT[k][h]
//   8 chunks of 98; within a chunk: in-order plain fp32 adds (products exact
//   for binary x); chunk partials combined in ascending chunk order.
// 512 threads = 16 warps; each warp owns 4 rows; each lane owns 8 h:
//   h = lane*4..+3 and 128+lane*4..+3 (conflict-free LDS.128).
// WiT chunk (98 x 256 fp32 = 100352 B) staged in dynamic smem.
// ---------------------------------------------------------------------------
#define K1_THREADS 512
#define RPW 4                        // rows per warp
#define RPC 64                       // rows per CTA
#define KCHUNK 98
#define NCHUNK 8
#define K1_SMEM (KCHUNK * HID * 4)   // 100352 bytes
#define CHUNK_F4 (KCHUNK * HID / 4)  // 6272 float4 per stage

__global__ __launch_bounds__(K1_THREADS, 1) void k1_xw(const float* __restrict__ x) {
    extern __shared__ float tile[];            // tile[kl*256 + h]
    const int tid  = threadIdx.x;
    const int lane = tid & 31;
    const int wrp  = tid >> 5;
    const int rbase = blockIdx.x * RPC + wrp * RPW;

    ull tot[RPW][4];                 // running split-K totals
#pragma unroll
    for (int r = 0; r < RPW; ++r)
#pragma unroll
        for (int j = 0; j < 4; ++j) tot[r][j] = 0ULL;

    for (int ch = 0; ch < NCHUNK; ++ch) {
        __syncthreads();
        const float4* src = (const float4*)(g_wiT + ch * KCHUNK * HID);
        float4* dst = (float4*)tile;
#pragma unroll
        for (int i = 0; i < 13; ++i) {
            int idx = tid + i * K1_THREADS;
            if (idx < CHUNK_F4) dst[idx] = src[idx];
        }
        __syncthreads();

#pragma unroll
        for (int r = 0; r < RPW; ++r) {
            const float* xr = x + (size_t)(rbase + r) * NIN + ch * KCHUNK;
            ull p0 = 0, p1 = 0, p2 = 0, p3 = 0;    // chunk partial
#pragma unroll
            for (int w4 = 0; w4 < 4; ++w4) {
                const bool lv = (w4 < 3) || (lane < 2);   // 98 = 3*32 + 2
                float xv = lv ? xr[w4 * 32 + lane] : 0.0f;
                unsigned m = __ballot_sync(0xffffffffu, xv != 0.0f);
                while (m) {
                    int kl = w4 * 32 + __ffs(m) - 1;
                    m &= m - 1;
                    ulonglong2 wa = *(const ulonglong2*)&tile[kl * HID + lane * 4];
                    ulonglong2 wb = *(const ulonglong2*)&tile[kl * HID + 128 + lane * 4];
                    p0 = f2_add(p0, wa.x);
                    p1 = f2_add(p1, wa.y);
                    p2 = f2_add(p2, wb.x);
                    p3 = f2_add(p3, wb.y);
                }
            }
            tot[r][0] = f2_add(tot[r][0], p0);   // ascending chunk combine
            tot[r][1] = f2_add(tot[r][1], p1);
            tot[r][2] = f2_add(tot[r][2], p2);
            tot[r][3] = f2_add(tot[r][3], p3);
        }
    }

#pragma unroll
    for (int r = 0; r < RPW; ++r) {
        float* o = g_xw + (size_t)(rbase + r) * HID;
        *(ulonglong2*)&o[lane * 4]       = make_ulonglong2(tot[r][0], tot[r][1]);
        *(ulonglong2*)&o[128 + lane * 4] = make_ulonglong2(tot[r][2], tot[r][3]);
    }
}

// ---------------------------------------------------------------------------
// LIF elementwise update, separately rounded fp32 ops (matches reference HLO)
// ---------------------------------------------------------------------------
__device__ __forceinline__ void lif_lane(float& v, float& i, float xw, float rec,
                                         unsigned& z) {
    float vd = __fadd_rn(v, __fmul_rn(0.05f, __fadd_rn(__fsub_rn(0.0f, v), i)));
    float id = __fmul_rn(i, 0.9f);
    z = vd > 0.5f;
    v = z ? 0.0f : vd;
    i = __fadd_rn(__fadd_rn(id, xw), rec);
}

// ---------------------------------------------------------------------------
// K2: persistent LIF recurrence. CTA owns 8 batch rows for all 50 steps.
// Recurrent drive = split-K=8 sum over WrT rows selected by the PREVIOUS
// step's spike bitmask: 8 chunks of 32 (one per mask word), in-order within
// a word, word partials combined ascending. Readout deferred via masks.
// ---------------------------------------------------------------------------
__global__ __launch_bounds__(256) void k2_steps(const float* __restrict__ Wout,
                                                const float* __restrict__ bout,
                                                float* __restrict__ out) {
    __shared__ uint32_t s_hist[T_STEPS][8][8];
    __shared__ uint8_t  s_nib[8][64];
    __shared__ float    s_part[80][3];

    const int tid = threadIdx.x;
    const int q   = tid & 63;
    const int p   = tid >> 6;
    const int b0  = blockIdx.x * 8;

    float4 v[2], cu[2];
    v[0]  = make_float4(0.f, 0.f, 0.f, 0.f);
    v[1]  = v[0];
    cu[0] = v[0];
    cu[1] = v[0];

    for (int t = 0; t < T_STEPS; ++t) {
#pragma unroll
        for (int rr = 0; rr < 2; ++rr) {
            const int r = p + rr * 4;
            const float4 xwv =
                *(const float4*)&g_xw[((size_t)(t * BATCH + b0 + r) * HID) + q * 4];

            // recurrent drive: split-K over 8 words of 32 spikes each
            ull rec0 = 0, rec1 = 0;
            if (t > 0) {
                const uint32_t* mrow = s_hist[t - 1][r];
#pragma unroll
                for (int w8 = 0; w8 < 8; ++w8) {
                    uint32_t m = mrow[w8];
                    ull p0 = 0, p1 = 0;             // word partial
                    while (m) {
                        int bpos = __ffs(m) - 1;
                        m &= m - 1;
                        ulonglong2 wr =
                            *(const ulonglong2*)&g_wrT[(w8 * 32 + bpos) * HID + q * 4];
                        p0 = f2_add(p0, wr.x);
                        p1 = f2_add(p1, wr.y);
                    }
                    rec0 = f2_add(rec0, p0);        // ascending combine
                    rec1 = f2_add(rec1, p1);
                }
            }
            float2 ra = *(float2*)&rec0;
            float2 rb = *(float2*)&rec1;

            unsigned zx, zy, zz, zw;
            lif_lane(v[rr].x, cu[rr].x, xwv.x, ra.x, zx);
            lif_lane(v[rr].y, cu[rr].y, xwv.y, ra.y, zy);
            lif_lane(v[rr].z, cu[rr].z, xwv.z, rb.x, zz);
            lif_lane(v[rr].w, cu[rr].w, xwv.w, rb.y, zw);
            s_nib[r][q] = (uint8_t)(zx | (zy << 1) | (zz << 2) | (zw << 3));
        }

        __syncthreads();
        if (tid < 64) {
            int r = tid >> 3, w = tid & 7;
            uint32_t word = 0;
#pragma unroll
            for (int j = 0; j < 8; ++j)
                word |= (uint32_t)s_nib[r][w * 8 + j] << (4 * j);
            s_hist[t][r][w] = word;
        }
        __syncthreads();
    }

    // deferred readout (no feedback; ordering perturbs only ~1e-7 relative)
    if (tid < 240) {
        int pair = tid / 3, seg = tid - pair * 3;
        int g = pair / NL, l = pair - g * NL;
        int t0 = seg * 17;
        int t1 = (seg == 2) ? T_STEPS : t0 + 17;
        float s = 0.0f;
        for (int t = t0; t < t1; ++t) {
#pragma unroll
            for (int w8 = 0; w8 < 8; ++w8) {
                uint32_t m = s_hist[t][g][w8];
                while (m) {
                    int bpos = __ffs(m) - 1;
                    m &= m - 1;
                    s = __fadd_rn(s, Wout[l * HID + w8 * 32 + bpos]);
                }
            }
        }
        s_part[pair][seg] = s;
    }
    __syncthreads();
    if (tid < 80) {
        int g = tid / NL, l = tid - (tid / NL) * NL;
        float a = __fadd_rn(__fadd_rn(s_part[tid][0], s_part[tid][1]), s_part[tid][2]);
        float val = __fdiv_rn(__fadd_rn(a, __fmul_rn((float)T_STEPS, bout[l])),
                              (float)T_STEPS);
        out[(b0 + g) * NL + l] = val;
    }
}

// ---------------------------------------------------------------------------
extern "C" void kernel_launch(void* const* d_in, const int* in_sizes, int n_in,
                              void* d_out, int out_size) {
    const float* x    = (const float*)d_in[0];
    const float* Wi   = (const float*)d_in[1];
    const float* Wr   = (const float*)d_in[2];
    const float* Wout = (const float*)d_in[3];
    const float* bout = (const float*)d_in[4];
    float* out = (float*)d_out;

    k0_prep<<<(NIN * HID + 255) / 256, 256>>>(Wi, Wr);

    static bool attr_set = false;
    if (!attr_set) {
        cudaFuncSetAttribute(k1_xw, cudaFuncAttributeMaxDynamicSharedMemorySize,
                             K1_SMEM);
        attr_set = true;
    }
    k1_xw<<<NROWS / RPC, K1_THREADS, K1_SMEM>>>(x);

    k2_steps<<<BATCH / 8, 256>>>(Wout, bout, out);
}